// round 8
// baseline (speedup 1.0000x reference)
#include <cuda_runtime.h>
#include <cuda_bf16.h>

// Problem constants
#define BB 8
#define SS 2048
#define FF 256
#define HH 8
#define DD 64
#define PROJ 512            // HH*DD
#define NSC 32              // s-chunks (64 rows each)
#define SCH 64              // rows per chunk

// Scratch (device globals — no allocation allowed)
__device__ float g_p[BB * HH * FF];             // p[b][h][f] = Wk_h @ q_last
__device__ float g_cm[BB * HH * NSC * 2];       // per-chunk (max, sumexp)
__device__ float g_yc[BB * NSC * HH * FF];      // unnormalized chunk sums (2MB)
__device__ float g_op[BB * 16 * FF];            // partial outputs per (h,fh)

// -------------------------------------------------------------------------
// K1: per (b,h): q_h = x[b,S-1,:] @ Wq[:,h*64:+64]; p[b,h,f] = Wk[f,h*64:].q_h
// grid: 64 blocks, 512 threads
// -------------------------------------------------------------------------
__global__ void k_prep(const float* __restrict__ x,
                       const float* __restrict__ Wq,
                       const float* __restrict__ Wk) {
    int blk = blockIdx.x;
    int b = blk >> 3, h = blk & 7;
    int t = threadIdx.x;
    __shared__ float xs[FF];
    __shared__ float qred[8 * DD];
    __shared__ float qs[DD];

    if (t < FF) xs[t] = x[((size_t)b * SS + (SS - 1)) * FF + t];
    __syncthreads();

    {   // q_h[d]: 512 threads = 64 d x 8 f-parts of 32
        int d = t & 63, part = t >> 6;
        const float* wq = Wq + (size_t)(part * 32) * PROJ + h * DD + d;
        const float* xf = xs + part * 32;
        float a = 0.f;
        #pragma unroll
        for (int f = 0; f < 32; ++f) a += xf[f] * wq[(size_t)f * PROJ];
        qred[part * DD + d] = a;
    }
    __syncthreads();
    if (t < DD) {
        float s = 0.f;
        #pragma unroll
        for (int p = 0; p < 8; ++p) s += qred[p * DD + t];
        qs[t] = s;
    }
    __syncthreads();

    int warp = t >> 5, lane = t & 31;
    float q0 = qs[lane], q1 = qs[32 + lane];
    #pragma unroll 4
    for (int i = 0; i < 16; ++i) {
        int f = warp + 16 * i;
        const float* wk = Wk + (size_t)f * PROJ + h * DD;
        float v = wk[lane] * q0 + wk[32 + lane] * q1;
        #pragma unroll
        for (int o = 16; o; o >>= 1) v += __shfl_xor_sync(0xFFFFFFFFu, v, o);
        if (lane == 0) g_p[(b * HH + h) * FF + f] = v;
    }
}

// -------------------------------------------------------------------------
// K2: flash pass — one read of x. Per (b, 64-row chunk):
//   Phase A: scores (16 warps x 4 rows = 64 rows, one iteration)
//   Stats:   warp-per-head local (m_c, d_c) -> g_cm
//   Phase B: yc[h][f] = sum_s exp(sc-m_c) * x[s][f]  (x re-read from L1)
// grid: BB*NSC = 256 blocks, 512 threads
// -------------------------------------------------------------------------
__global__ void k_flash(const float* __restrict__ x) {
    int blk = blockIdx.x;
    int b = blk >> 5;
    int chunk = blk & 31;
    int t = threadIdx.x;
    int warp = t >> 5, lane = t & 31;
    __shared__ float ps[HH * FF];       // 8KB
    __shared__ float sbuf[HH][SCH];     // 2KB
    __shared__ float ws[HH][SCH];       // 2KB
    __shared__ float mh[HH];

    for (int i = t; i < HH * FF; i += 512) ps[i] = g_p[b * HH * FF + i];
    __syncthreads();

    const float4* ps4 = (const float4*)ps;
    const float4* xr_base = (const float4*)(x + ((size_t)b * SS + chunk * SCH) * FF);

    // ---- Phase A: scores, warp w -> rows [w*4, w*4+4) ----
    {
        int r0 = warp * 4;
        const float4* xr = xr_base + (size_t)r0 * 64;

        float4 a[4], c[4];
        #pragma unroll
        for (int r = 0; r < 4; ++r) {
            a[r] = xr[r * 64 + lane];
            c[r] = xr[r * 64 + 32 + lane];
        }

        #pragma unroll
        for (int r = 0; r < 4; ++r) {
            float dot[HH];
            #pragma unroll
            for (int h = 0; h < HH; ++h) {
                float4 pa = ps4[h * 64 + lane];
                float4 pc = ps4[h * 64 + 32 + lane];
                dot[h] = a[r].x * pa.x + a[r].y * pa.y + a[r].z * pa.z + a[r].w * pa.w
                       + c[r].x * pc.x + c[r].y * pc.y + c[r].z * pc.z + c[r].w * pc.w;
            }
            #pragma unroll
            for (int h = 0; h < HH; ++h) {
                #pragma unroll
                for (int o = 16; o; o >>= 1)
                    dot[h] += __shfl_xor_sync(0xFFFFFFFFu, dot[h], o);
            }
            if (lane == 0) {
                #pragma unroll
                for (int h = 0; h < HH; ++h)
                    sbuf[h][r0 + r] = dot[h] * 0.125f;
            }
        }
    }
    __syncthreads();

    // ---- local stats: warp h handles head h (lanes cover 64 s) ----
    if (warp < HH) {
        int h = warp;
        float v0 = sbuf[h][lane], v1 = sbuf[h][lane + 32];
        float m = fmaxf(v0, v1);
        #pragma unroll
        for (int o = 16; o; o >>= 1) m = fmaxf(m, __shfl_xor_sync(0xFFFFFFFFu, m, o));
        float s = __expf(v0 - m) + __expf(v1 - m);
        #pragma unroll
        for (int o = 16; o; o >>= 1) s += __shfl_xor_sync(0xFFFFFFFFu, s, o);
        if (lane == 0) {
            int idx = ((b * HH + h) * NSC + chunk) * 2;
            g_cm[idx] = m;
            g_cm[idx + 1] = s;
            mh[h] = m;
        }
    }
    __syncthreads();

    // ---- unnormalized weights: 512 threads = HH*SCH ----
    {
        int h = t >> 6, s = t & 63;
        ws[h][s] = __expf(sbuf[h][s] - mh[h]);
    }
    __syncthreads();

    // ---- Phase B: thread = (head h = t>>6, f4 = t&63), x hits L1 ----
    int f4 = t & 63, h = t >> 6;
    float4 acc = make_float4(0.f, 0.f, 0.f, 0.f);
    const float* wrow = ws[h];

    #pragma unroll 8
    for (int s = 0; s < SCH; ++s) {
        float4 xv = xr_base[(size_t)s * 64 + f4];
        float w = wrow[s];
        acc.x += w * xv.x; acc.y += w * xv.y; acc.z += w * xv.z; acc.w += w * xv.w;
    }

    float4* out4 = (float4*)(g_yc + ((size_t)(b * NSC + chunk)) * (HH * FF));
    out4[h * 64 + f4] = acc;
}

// -------------------------------------------------------------------------
// K3: per (b,h,fh): y_half = (sum_c exp(m_c-M) yc[c][.]) / D;
//     attn_h partial = y_half @ Wv[fh-half, h]; then project through Wo:
//     op[b][(h,fh)][j] = sum_d attn_h[d] * Wo[h*64+d][j]
// grid: BB*HH*2 = 128 blocks, 512 threads
// -------------------------------------------------------------------------
__global__ void k_proj(const float* __restrict__ Wv,
                       const float* __restrict__ Wo) {
    int blk = blockIdx.x;
    int b = blk >> 4;
    int h = (blk >> 1) & 7;
    int fh = blk & 1;
    int t = threadIdx.x;
    __shared__ float scales[NSC];
    __shared__ float stats[1];          // invD
    __shared__ float red[3][128];
    __shared__ float ys[128];
    __shared__ float ared[8][DD];
    __shared__ float attn_s[DD];
    __shared__ float4 red4[7][64];      // 7KB

    if (t < 32) {   // warp 0: global stats + per-chunk scales
        const float* cm = g_cm + (size_t)(b * HH + h) * NSC * 2;
        float m = cm[t * 2], d = cm[t * 2 + 1];
        float M = m;
        #pragma unroll
        for (int o = 16; o; o >>= 1) M = fmaxf(M, __shfl_xor_sync(0xFFFFFFFFu, M, o));
        float e = __expf(m - M);
        scales[t] = e;
        float ds = d * e;
        #pragma unroll
        for (int o = 16; o; o >>= 1) ds += __shfl_xor_sync(0xFFFFFFFFu, ds, o);
        if (t == 0) stats[0] = 1.f / ds;
    }
    __syncthreads();
    float invD = stats[0];

    {   // y-half: 512 threads = 128 f x 4 chunk-groups of 8
        int f = t & 127, cg = t >> 7;
        const float* pp = g_yc + ((size_t)(b * NSC + cg * 8) * HH + h) * FF + fh * 128 + f;
        float s = 0.f;
        #pragma unroll
        for (int c = 0; c < 8; ++c)
            s += scales[cg * 8 + c] * pp[(size_t)c * (HH * FF)];
        if (cg > 0) red[cg - 1][f] = s;
        __syncthreads();
        if (cg == 0) ys[f] = (s + red[0][f] + red[1][f] + red[2][f]) * invD;
    }
    __syncthreads();

    {   // partial attn: 512 threads = 64 d x 8 f-parts of 16
        int d = t & 63, part = t >> 6;
        const float* wv = Wv + (size_t)(fh * 128 + part * 16) * PROJ + h * DD + d;
        const float* yf = ys + part * 16;
        float a = 0.f;
        #pragma unroll
        for (int f = 0; f < 16; ++f) a += yf[f] * wv[(size_t)f * PROJ];
        ared[part][d] = a;
    }
    __syncthreads();
    if (t < DD) {
        float s = 0.f;
        #pragma unroll
        for (int p = 0; p < 8; ++p) s += ared[p][t];
        attn_s[t] = s;
    }
    __syncthreads();

    {   // Wo projection: 512 threads = 64 j4 x 8 d-parts of 8
        int j4 = t & 63, dp = t >> 6;
        const float4* wo4 = (const float4*)Wo + (size_t)(h * DD + dp * 8) * 64 + j4;
        const float* ad = attn_s + dp * 8;
        float4 acc = make_float4(0.f, 0.f, 0.f, 0.f);
        #pragma unroll
        for (int i = 0; i < 8; ++i) {
            float a = ad[i];
            float4 w = wo4[(size_t)i * 64];
            acc.x += a * w.x; acc.y += a * w.y; acc.z += a * w.z; acc.w += a * w.w;
        }
        if (dp > 0) red4[dp - 1][j4] = acc;
        __syncthreads();
        if (dp == 0) {
            #pragma unroll
            for (int g = 0; g < 7; ++g) {
                float4 o = red4[g][j4];
                acc.x += o.x; acc.y += o.y; acc.z += o.z; acc.w += o.w;
            }
            float4* op = (float4*)g_op + (size_t)(b * 16 + h * 2 + fh) * 64 + j4;
            *op = acc;
        }
    }
}

// -------------------------------------------------------------------------
// K4: out[b,j] = sum_{p<16} op[b][p][j] + bo[j]
// grid: BB blocks, 256 threads
// -------------------------------------------------------------------------
__global__ void k_sum(const float* __restrict__ bo,
                      float* __restrict__ out) {
    int b = blockIdx.x, t = threadIdx.x;
    const float* pp = g_op + (size_t)b * 16 * FF + t;
    float s = bo[t];
    #pragma unroll
    for (int p = 0; p < 16; ++p) s += pp[(size_t)p * FF];
    out[(size_t)b * FF + t] = s;
}

// -------------------------------------------------------------------------
extern "C" void kernel_launch(void* const* d_in, const int* in_sizes, int n_in,
                              void* d_out, int out_size) {
    const float* x  = (const float*)d_in[0];
    const float* Wq = (const float*)d_in[1];
    const float* Wk = (const float*)d_in[2];
    const float* Wv = (const float*)d_in[3];
    const float* Wo = (const float*)d_in[4];
    const float* bo = (const float*)d_in[5];
    float* out = (float*)d_out;

    k_prep<<<BB * HH, 512>>>(x, Wq, Wk);
    k_flash<<<BB * NSC, 512>>>(x);
    k_proj<<<BB * HH * 2, 512>>>(Wv, Wo);
    k_sum<<<BB, 256>>>(bo, out);
}